// round 11
// baseline (speedup 1.0000x reference)
#include <cuda_runtime.h>
#include <cuda_fp16.h>
#include <cstdint>
#include <math.h>

#define NN 50000
#define EE 200000
#define SCAN_BS 512
#define SCAN_NB 98          // ceil(NN/512)

// ---------------- scratch (static device globals; allocation-free) ----------------
__device__ float   g_bufA[(size_t)NN * 1024];
__device__ float   g_bufB[(size_t)NN * 1024];
__device__ __half  g_AhA[(size_t)NN * 1024];
__device__ __half  g_AhB[(size_t)NN * 1024];
__device__ uint8_t g_A8hA[(size_t)NN * 1024];
__device__ uint8_t g_A8lA[(size_t)NN * 1024];
__device__ uint8_t g_A8hB[(size_t)NN * 1024];
__device__ uint8_t g_A8lB[(size_t)NN * 1024];
__device__ __half  g_Wh[1024 * 1024];
__device__ uint8_t g_W8h[1024 * 1024];
__device__ uint8_t g_W8l[1024 * 1024];
__device__ int   g_cnt[NN];
__device__ int   g_cur[NN];
__device__ int   g_off[NN + 1];
__device__ int   g_bsum[SCAN_NB];
__device__ float g_dis[NN];
__device__ int   g_src[EE];
__device__ float g_enrm[EE];

#define RES_SCALE 2048.0f
#define RES_ISCALE 4.8828125e-4f   // 1/2048

// ================= PTX helpers (arch-generic: sm_80/89+) =================
__device__ __forceinline__ uint32_t smem_to_u32(const void* p) {
    uint32_t a;
    asm("{ .reg .u64 t; cvta.to.shared.u64 t, %1; cvt.u32.u64 %0, t; }" : "=r"(a) : "l"(p));
    return a;
}
#define CP_ASYNC16(dst, src) \
    asm volatile("cp.async.cg.shared.global [%0], [%1], 16;" :: "r"(dst), "l"(src))
#define CP_COMMIT() asm volatile("cp.async.commit_group;" ::: "memory")
#define CP_WAIT(n)  asm volatile("cp.async.wait_group %0;" :: "n"(n) : "memory")
#define LDSM_X4(r0, r1, r2, r3, addr) \
    asm volatile("ldmatrix.sync.aligned.m8n8.x4.shared.b16 {%0,%1,%2,%3}, [%4];" \
        : "=r"(r0), "=r"(r1), "=r"(r2), "=r"(r3) : "r"(addr))
#define MMA_16816(c, a, b) \
    asm volatile("mma.sync.aligned.m16n8k16.row.col.f32.f16.f16.f32 " \
        "{%0,%1,%2,%3}, {%4,%5,%6,%7}, {%8,%9}, {%0,%1,%2,%3};" \
        : "+f"((c)[0]), "+f"((c)[1]), "+f"((c)[2]), "+f"((c)[3]) \
        : "r"((a)[0]), "r"((a)[1]), "r"((a)[2]), "r"((a)[3]), "r"((b)[0]), "r"((b)[1]))
// fp8 e4m3 mma, zero-C and accumulate forms
#define QMMA_Z(d, a, b) \
    asm volatile("mma.sync.aligned.m16n8k32.row.col.f32.e4m3.e4m3.f32 " \
        "{%0,%1,%2,%3}, {%4,%5,%6,%7}, {%8,%9}, {%10,%10,%10,%10};" \
        : "=f"((d)[0]), "=f"((d)[1]), "=f"((d)[2]), "=f"((d)[3]) \
        : "r"((a)[0]), "r"((a)[1]), "r"((a)[2]), "r"((a)[3]), "r"((b)[0]), "r"((b)[1]), \
          "f"(0.0f))
#define QMMA_A(d, a, b) \
    asm volatile("mma.sync.aligned.m16n8k32.row.col.f32.e4m3.e4m3.f32 " \
        "{%0,%1,%2,%3}, {%4,%5,%6,%7}, {%8,%9}, {%0,%1,%2,%3};" \
        : "+f"((d)[0]), "+f"((d)[1]), "+f"((d)[2]), "+f"((d)[3]) \
        : "r"((a)[0]), "r"((a)[1]), "r"((a)[2]), "r"((a)[3]), "r"((b)[0]), "r"((b)[1]))
// pack two floats into e4m3x2 (hi -> upper byte, lo -> lower byte)
__device__ __forceinline__ uint32_t f2e4m3x2(float hi, float lo) {
    uint16_t v;
    asm("cvt.rn.satfinite.e4m3x2.f32 %0, %1, %2;" : "=h"(v) : "f"(hi), "f"(lo));
    return (uint32_t)v;
}

// ================= CSR build =================
__global__ void k_zero2(int* __restrict__ a, int* __restrict__ b) {
    int i = blockIdx.x * blockDim.x + threadIdx.x;
    if (i < NN) { a[i] = 0; b[i] = 0; }
}
__global__ void k_cnt(const int* __restrict__ col, int* __restrict__ cnt) {
    int e = blockIdx.x * blockDim.x + threadIdx.x;
    if (e < EE) atomicAdd(&cnt[col[e]], 1);
}
__global__ void k_scan1(const int* __restrict__ cnt, int* __restrict__ off,
                        int* __restrict__ bsum) {
    __shared__ int sh[SCAN_BS];
    int tid = threadIdx.x;
    int i = blockIdx.x * SCAN_BS + tid;
    int v = (i < NN) ? cnt[i] : 0;
    sh[tid] = v;
    __syncthreads();
    #pragma unroll
    for (int d = 1; d < SCAN_BS; d <<= 1) {
        int t = (tid >= d) ? sh[tid - d] : 0;
        __syncthreads();
        sh[tid] += t;
        __syncthreads();
    }
    if (i < NN) off[i] = sh[tid] - v;
    if (tid == SCAN_BS - 1) bsum[blockIdx.x] = sh[tid];
}
__global__ void k_scan2(int* __restrict__ bsum) {
    __shared__ int sh[128];
    int tid = threadIdx.x;
    int v = (tid < SCAN_NB) ? bsum[tid] : 0;
    sh[tid] = v;
    __syncthreads();
    #pragma unroll
    for (int d = 1; d < 128; d <<= 1) {
        int t = (tid >= d) ? sh[tid - d] : 0;
        __syncthreads();
        sh[tid] += t;
        __syncthreads();
    }
    if (tid < SCAN_NB) bsum[tid] = sh[tid] - v;
}
__global__ void k_scan3(int* __restrict__ off, const int* __restrict__ bsum) {
    int i = blockIdx.x * blockDim.x + threadIdx.x;
    if (i < NN) off[i] += bsum[i / SCAN_BS];
    if (i == 0) off[NN] = EE;
}
__global__ void k_disk(const int* __restrict__ cnt, float* __restrict__ dis) {
    int i = blockIdx.x * blockDim.x + threadIdx.x;
    if (i < NN) dis[i] = rsqrtf((float)(cnt[i] + 1));
}
__global__ void k_fill(const int* __restrict__ row, const int* __restrict__ col,
                       const float* __restrict__ dis, const int* __restrict__ off,
                       int* __restrict__ cur, int* __restrict__ src,
                       float* __restrict__ enrm) {
    int e = blockIdx.x * blockDim.x + threadIdx.x;
    if (e >= EE) return;
    int r = row[e], c = col[e];
    int pos = off[c] + atomicAdd(&cur[c], 1);
    src[pos] = r;
    enrm[pos] = dis[r] * dis[c];
}

// ================= fused CSR gather aggregation =================
// SPLIT: write fp16-hi + fp8(value) + fp8(residual*2048) trio.
template <int F, bool BIAS, bool RELU, bool SPLIT>
__global__ void __launch_bounds__(256) k_gather4(
    const float4* __restrict__ h, const int* __restrict__ off,
    const int* __restrict__ src, const float* __restrict__ enrm,
    const float* __restrict__ dis, const float* __restrict__ bias,
    float4* __restrict__ outf, __half2* __restrict__ ohi,
    uint32_t* __restrict__ o8h, uint32_t* __restrict__ o8l) {
    constexpr int FV = F / 4;
    int idx = blockIdx.x * blockDim.x + threadIdx.x;
    if (idx >= NN * FV) return;
    int i = idx / FV;
    int f4 = idx - i * FV;
    float d = dis[i];
    float s = d * d;
    float4 v = h[(size_t)i * FV + f4];
    float4 acc;
    acc.x = s * v.x; acc.y = s * v.y; acc.z = s * v.z; acc.w = s * v.w;
    int p0 = off[i], p1 = off[i + 1];
    for (int p = p0; p < p1; p++) {
        int sn = src[p];
        float w = enrm[p];
        float4 u = h[(size_t)sn * FV + f4];
        acc.x += w * u.x; acc.y += w * u.y; acc.z += w * u.z; acc.w += w * u.w;
    }
    if (BIAS) {
        const float4 bv = *(const float4*)(bias + f4 * 4);
        acc.x += bv.x; acc.y += bv.y; acc.z += bv.z; acc.w += bv.w;
    }
    if (RELU) {
        acc.x = fmaxf(acc.x, 0.f); acc.y = fmaxf(acc.y, 0.f);
        acc.z = fmaxf(acc.z, 0.f); acc.w = fmaxf(acc.w, 0.f);
    }
    if (SPLIT) {
        __half hx = __float2half(acc.x), hy = __float2half(acc.y);
        __half hz = __float2half(acc.z), hw = __float2half(acc.w);
        ohi[(size_t)idx * 2 + 0] = __halves2half2(hx, hy);
        ohi[(size_t)idx * 2 + 1] = __halves2half2(hz, hw);
        float lx = (acc.x - __half2float(hx)) * RES_SCALE;
        float ly = (acc.y - __half2float(hy)) * RES_SCALE;
        float lz = (acc.z - __half2float(hz)) * RES_SCALE;
        float lw = (acc.w - __half2float(hw)) * RES_SCALE;
        o8h[idx] = (f2e4m3x2(acc.w, acc.z) << 16) | f2e4m3x2(acc.y, acc.x);
        o8l[idx] = (f2e4m3x2(lw, lz) << 16) | f2e4m3x2(ly, lx);
    } else {
        outf[idx] = acc;
    }
}

// scalar variant for F=3 and F=2
template <int F, bool BIAS>
__global__ void k_gather1(const float* __restrict__ h, const int* __restrict__ off,
                          const int* __restrict__ src, const float* __restrict__ enrm,
                          const float* __restrict__ dis, const float* __restrict__ bias,
                          float* __restrict__ outf) {
    int idx = blockIdx.x * blockDim.x + threadIdx.x;
    if (idx >= NN * F) return;
    int i = idx / F;
    int f = idx - i * F;
    float d = dis[i];
    float acc = d * d * h[(size_t)i * F + f];
    int p0 = off[i], p1 = off[i + 1];
    for (int p = p0; p < p1; p++)
        acc += enrm[p] * h[(size_t)src[p] * F + f];
    if (BIAS) acc += bias[f];
    outf[idx] = acc;
}

// ================= weight split: W [K,N] fp32 -> [N,K] fp16-hi + fp8 + fp8-res =================
__global__ void k_wsplit(const float* __restrict__ W, __half* __restrict__ Wh,
                         uint8_t* __restrict__ W8h, uint8_t* __restrict__ W8l,
                         int K, int N) {
    int idx = blockIdx.x * blockDim.x + threadIdx.x;
    if (idx >= N * K) return;
    int n = idx / K;
    int k = idx - n * K;
    float v = W[(size_t)k * N + n];
    __half h = __float2half(v);
    Wh[idx] = h;
    float wl = (v - __half2float(h)) * RES_SCALE;
    W8h[idx] = (uint8_t)(f2e4m3x2(0.f, v) & 0xFFu);
    W8l[idx] = (uint8_t)(f2e4m3x2(0.f, wl) & 0xFFu);
}

// ================= mixed fp16/fp8 mma GEMM =================
// C = Ah16*Wh16 (fp16 HMMA) + [ (Al*2048)*W + A*(Wl*2048) ] in fp8 QMMA k32, folded /2048.
// CTA 128x256, BK=32, 8 warps (2m x 4n), warp tile 64x64, 2-stage cp.async.
// Stage (67584 B): [A16 10240][A8h 6144][A8l 6144][B16 20480][B8h 12288][B8l 12288]
#define R16 80
#define R8  48
#define O_A16 0
#define O_A8H 10240
#define O_A8L 16384
#define O_B16 22528
#define O_B8H 43008
#define O_B8L 55296
#define MG_ST 67584
#define MG_SMEM (2 * MG_ST)

__device__ __forceinline__ void mg_load6(
    const __half* __restrict__ Ah_, const uint8_t* __restrict__ A8h_,
    const uint8_t* __restrict__ A8l_, const __half* __restrict__ Bh_,
    const uint8_t* __restrict__ B8h_, const uint8_t* __restrict__ B8l_,
    int M, int K, int bm, int bn, int koff, uint32_t st, int tid) {
    // A16: 128 rows x 64B
    #pragma unroll
    for (int i = 0; i < 2; i++) {
        int idx = tid + i * 256;
        int r = idx >> 2, ch = idx & 3;
        int gr = bm + r; if (gr >= M) gr = M - 1;
        CP_ASYNC16(st + O_A16 + r * R16 + ch * 16,
                   (const void*)(Ah_ + (size_t)gr * K + koff + ch * 8));
    }
    // A8h / A8l: 128 rows x 32B
    {
        int r = tid >> 1, ch = tid & 1;
        int gr = bm + r; if (gr >= M) gr = M - 1;
        CP_ASYNC16(st + O_A8H + r * R8 + ch * 16,
                   (const void*)(A8h_ + (size_t)gr * K + koff + ch * 16));
        CP_ASYNC16(st + O_A8L + r * R8 + ch * 16,
                   (const void*)(A8l_ + (size_t)gr * K + koff + ch * 16));
    }
    // B16: 256 rows x 64B
    #pragma unroll
    for (int i = 0; i < 4; i++) {
        int idx = tid + i * 256;
        int r = idx >> 2, ch = idx & 3;
        CP_ASYNC16(st + O_B16 + r * R16 + ch * 16,
                   (const void*)(Bh_ + (size_t)(bn + r) * K + koff + ch * 8));
    }
    // B8h / B8l: 256 rows x 32B
    #pragma unroll
    for (int i = 0; i < 2; i++) {
        int idx = tid + i * 256;
        int r = idx >> 1, ch = idx & 1;
        CP_ASYNC16(st + O_B8H + r * R8 + ch * 16,
                   (const void*)(B8h_ + (size_t)(bn + r) * K + koff + ch * 16));
        CP_ASYNC16(st + O_B8L + r * R8 + ch * 16,
                   (const void*)(B8l_ + (size_t)(bn + r) * K + koff + ch * 16));
    }
    CP_COMMIT();
}

template <bool BIAS_RELU, bool SPLIT>
__global__ void __launch_bounds__(256) k_mma_gemm(
    const __half* __restrict__ Ahi, const uint8_t* __restrict__ A8h,
    const uint8_t* __restrict__ A8l, const __half* __restrict__ Bhi,
    const uint8_t* __restrict__ B8h, const uint8_t* __restrict__ B8l,
    const float* __restrict__ bias, float* __restrict__ Cf,
    __half2* __restrict__ Chh, uint16_t* __restrict__ C8h, uint16_t* __restrict__ C8l,
    int M, int N, int K) {
    extern __shared__ __align__(16) char smx[];
    const uint32_t sbase = smem_to_u32(smx);
    const int tid = threadIdx.x;
    const int lane = tid & 31;
    const int wid = tid >> 5;
    const int wm = (wid & 1) * 64;
    const int wn = (wid >> 1) * 64;
    const int bm = blockIdx.y * 128;
    const int bn = blockIdx.x * 256;

    const int CK = K / 32;

    float acc[4][8][4];
    #pragma unroll
    for (int i = 0; i < 4; i++)
        #pragma unroll
        for (int j = 0; j < 8; j++)
            #pragma unroll
            for (int q = 0; q < 4; q++) acc[i][j][q] = 0.f;

    mg_load6(Ahi, A8h, A8l, Bhi, B8h, B8l, M, K, bm, bn, 0, sbase, tid);

    for (int c = 0; c < CK; c++) {
        const int s = c & 1;
        if (c + 1 < CK) {
            mg_load6(Ahi, A8h, A8l, Bhi, B8h, B8l, M, K, bm, bn, (c + 1) * 32,
                     sbase + (s ^ 1) * MG_ST, tid);
            CP_WAIT(1);
        } else {
            CP_WAIT(0);
        }
        __syncthreads();

        const uint32_t base = sbase + s * MG_ST;
        // ---- main product: fp16 HMMA, 2 k-steps ----
        #pragma unroll
        for (int kk = 0; kk < 32; kk += 16) {
            uint32_t ah[4][4];
            #pragma unroll
            for (int mi = 0; mi < 4; mi++) {
                int r = wm + mi * 16 + (lane & 15);
                int colb = (kk + ((lane >> 4) << 3)) * 2;
                LDSM_X4(ah[mi][0], ah[mi][1], ah[mi][2], ah[mi][3],
                        base + O_A16 + r * R16 + colb);
            }
            uint32_t bh[8][2];
            #pragma unroll
            for (int nb = 0; nb < 4; nb++) {
                int n = wn + nb * 16 + (lane & 7) + ((lane >> 4) << 3);
                int colb = (kk + (((lane >> 3) & 1) << 3)) * 2;
                LDSM_X4(bh[2 * nb][0], bh[2 * nb][1], bh[2 * nb + 1][0], bh[2 * nb + 1][1],
                        base + O_B16 + n * R16 + colb);
            }
            #pragma unroll
            for (int mi = 0; mi < 4; mi++)
                #pragma unroll
                for (int nj = 0; nj < 8; nj++)
                    MMA_16816(acc[mi][nj], ah[mi], bh[nj]);
        }
        // ---- corrections: fp8 QMMA k32 (whole chunk in one step) ----
        {
            uint32_t c8h[8][2], c8l[8][2];
            #pragma unroll
            for (int p = 0; p < 4; p++) {
                int n = wn + p * 16 + ((lane >> 4) << 3) + (lane & 7);
                int bo = ((lane >> 3) & 1) * 16;
                LDSM_X4(c8h[2 * p][0], c8h[2 * p][1], c8h[2 * p + 1][0], c8h[2 * p + 1][1],
                        base + O_B8H + n * R8 + bo);
                LDSM_X4(c8l[2 * p][0], c8l[2 * p][1], c8l[2 * p + 1][0], c8l[2 * p + 1][1],
                        base + O_B8L + n * R8 + bo);
            }
            #pragma unroll
            for (int mi = 0; mi < 4; mi++) {
                int ar = (wm + mi * 16 + (lane & 15)) * R8 + ((lane >> 4) << 4);
                uint32_t a8h_[4], a8l_[4];
                LDSM_X4(a8h_[0], a8h_[1], a8h_[2], a8h_[3], base + O_A8H + ar);
                LDSM_X4(a8l_[0], a8l_[1], a8l_[2], a8l_[3], base + O_A8L + ar);
                float cr[8][4];
                #pragma unroll
                for (int nj = 0; nj < 8; nj++) {
                    QMMA_Z(cr[nj], a8l_, c8h[nj]);   // (Al*2048) * Wh
                    QMMA_A(cr[nj], a8h_, c8l[nj]);   // A * (Wl*2048)
                }
                #pragma unroll
                for (int nj = 0; nj < 8; nj++)
                    #pragma unroll
                    for (int q = 0; q < 4; q++)
                        acc[mi][nj][q] += cr[nj][q] * RES_ISCALE;
            }
        }
        __syncthreads();
    }

    // epilogue
    #pragma unroll
    for (int mi = 0; mi < 4; mi++) {
        int r0 = bm + wm + mi * 16 + (lane >> 2);
        #pragma unroll
        for (int nj = 0; nj < 8; nj++) {
            int cn = bn + wn + nj * 8 + (lane & 3) * 2;
            float2 v0, v1;
            v0.x = acc[mi][nj][0]; v0.y = acc[mi][nj][1];
            v1.x = acc[mi][nj][2]; v1.y = acc[mi][nj][3];
            if (BIAS_RELU) {
                float b0 = bias[cn], b1 = bias[cn + 1];
                v0.x = fmaxf(v0.x + b0, 0.f); v0.y = fmaxf(v0.y + b1, 0.f);
                v1.x = fmaxf(v1.x + b0, 0.f); v1.y = fmaxf(v1.y + b1, 0.f);
            }
            if (SPLIT) {
                #pragma unroll
                for (int rr = 0; rr < 2; rr++) {
                    int r = r0 + rr * 8;
                    if (r < M) {
                        float2 v = rr ? v1 : v0;
                        __half hx = __float2half(v.x), hy = __float2half(v.y);
                        float lx = (v.x - __half2float(hx)) * RES_SCALE;
                        float ly = (v.y - __half2float(hy)) * RES_SCALE;
                        size_t o = ((size_t)r * N + cn) >> 1;
                        Chh[o] = __halves2half2(hx, hy);
                        C8h[o] = (uint16_t)f2e4m3x2(v.y, v.x);
                        C8l[o] = (uint16_t)f2e4m3x2(ly, lx);
                    }
                }
            } else {
                if (r0 < M)     *(float2*)(Cf + (size_t)r0 * N + cn) = v0;
                if (r0 + 8 < M) *(float2*)(Cf + (size_t)(r0 + 8) * N + cn) = v1;
            }
        }
    }
}

// ================= SIMT GEMM (small layers L1-L3) =================
template <bool RELU, bool BIAS>
__global__ void __launch_bounds__(256) k_gemm(
    const float* __restrict__ A, const float* __restrict__ B,
    const float* __restrict__ bias, float* __restrict__ C,
    int M, int N, int K) {
    constexpr int BMx = 128, BNx = 64, BK = 16, TM = 8, TN = 4;
    constexpr int AST = BMx + 4;
    __shared__ float As[BK * AST];
    __shared__ float Bs[BK * BNx];
    const int tid = threadIdx.x;
    const int bm = blockIdx.y * BMx;
    const int bn = blockIdx.x * BNx;
    const int tx = tid & 15;
    const int ty = tid >> 4;
    const int ar = tid >> 2;
    const int ac = (tid & 3) * 4;
    const int br = tid >> 4;
    const int bc = (tid & 15) * 4;
    float acc[TM][TN] = {};
    for (int kt = 0; kt < K; kt += BK) {
        #pragma unroll
        for (int i = 0; i < 2; i++) {
            int r = ar + i * 64;
            int gr = bm + r;
            float4 v = make_float4(0.f, 0.f, 0.f, 0.f);
            if (gr < M) v = *(const float4*)(A + (size_t)gr * K + kt + ac);
            As[(ac + 0) * AST + r] = v.x;
            As[(ac + 1) * AST + r] = v.y;
            As[(ac + 2) * AST + r] = v.z;
            As[(ac + 3) * AST + r] = v.w;
        }
        {
            float4 v = *(const float4*)(B + (size_t)(kt + br) * N + bn + bc);
            *(float4*)(Bs + br * BNx + bc) = v;
        }
        __syncthreads();
        #pragma unroll
        for (int k = 0; k < BK; k++) {
            float ra[TM], rb[TN];
            float4 a0 = *(const float4*)(As + k * AST + ty * TM);
            float4 a1 = *(const float4*)(As + k * AST + ty * TM + 4);
            ra[0] = a0.x; ra[1] = a0.y; ra[2] = a0.z; ra[3] = a0.w;
            ra[4] = a1.x; ra[5] = a1.y; ra[6] = a1.z; ra[7] = a1.w;
            float4 b0 = *(const float4*)(Bs + k * BNx + tx * TN);
            rb[0] = b0.x; rb[1] = b0.y; rb[2] = b0.z; rb[3] = b0.w;
            #pragma unroll
            for (int m = 0; m < TM; m++)
                #pragma unroll
                for (int n = 0; n < TN; n++)
                    acc[m][n] += ra[m] * rb[n];
        }
        __syncthreads();
    }
    float bv[TN] = {0.f, 0.f, 0.f, 0.f};
    if (BIAS) {
        float4 t = *(const float4*)(bias + bn + tx * TN);
        bv[0] = t.x; bv[1] = t.y; bv[2] = t.z; bv[3] = t.w;
    }
    #pragma unroll
    for (int m = 0; m < TM; m++) {
        int gr = bm + ty * TM + m;
        if (gr < M) {
            float4 o;
            o.x = acc[m][0] + bv[0];
            o.y = acc[m][1] + bv[1];
            o.z = acc[m][2] + bv[2];
            o.w = acc[m][3] + bv[3];
            if (RELU) {
                o.x = fmaxf(o.x, 0.f); o.y = fmaxf(o.y, 0.f);
                o.z = fmaxf(o.z, 0.f); o.w = fmaxf(o.w, 0.f);
            }
            *(float4*)(C + (size_t)gr * N + bn + tx * TN) = o;
        }
    }
}

// ---------------- layer-0 GEMM (K=3, Fout=64, bias+relu) ----------------
__global__ void k_l0_gemm(const float* __restrict__ t, const float* __restrict__ W,
                          const float* __restrict__ b, float* __restrict__ y) {
    int idx = blockIdx.x * blockDim.x + threadIdx.x;
    if (idx >= NN * 64) return;
    int i = idx >> 6;
    int j = idx & 63;
    float acc = b[j];
    acc += t[i * 3 + 0] * W[0 * 64 + j];
    acc += t[i * 3 + 1] * W[1 * 64 + j];
    acc += t[i * 3 + 2] * W[2 * 64 + j];
    y[idx] = fmaxf(acc, 0.f);
}

// ---------------- layer-7 GEMM (K=256, Fout=2) with fused input relu ----
__global__ void k_l7_gemm(const float* __restrict__ x, const float* __restrict__ W,
                          float* __restrict__ h) {
    int gwarp = (blockIdx.x * blockDim.x + threadIdx.x) >> 5;
    int lane = threadIdx.x & 31;
    if (gwarp >= NN) return;
    const float4* xr = (const float4*)(x + (size_t)gwarp * 256);
    float a0 = 0.f, a1 = 0.f;
    #pragma unroll
    for (int it = 0; it < 2; it++) {
        int c4 = lane + it * 32;
        float4 v = xr[c4];
        v.x = fmaxf(v.x, 0.f); v.y = fmaxf(v.y, 0.f);
        v.z = fmaxf(v.z, 0.f); v.w = fmaxf(v.w, 0.f);
        int k = c4 * 4;
        a0 += v.x * W[(k + 0) * 2 + 0] + v.y * W[(k + 1) * 2 + 0]
            + v.z * W[(k + 2) * 2 + 0] + v.w * W[(k + 3) * 2 + 0];
        a1 += v.x * W[(k + 0) * 2 + 1] + v.y * W[(k + 1) * 2 + 1]
            + v.z * W[(k + 2) * 2 + 1] + v.w * W[(k + 3) * 2 + 1];
    }
    #pragma unroll
    for (int off = 16; off > 0; off >>= 1) {
        a0 += __shfl_down_sync(0xFFFFFFFFu, a0, off);
        a1 += __shfl_down_sync(0xFFFFFFFFu, a1, off);
    }
    if (lane == 0) {
        h[gwarp * 2 + 0] = a0;
        h[gwarp * 2 + 1] = a1;
    }
}

// ================= host orchestration =================
extern "C" void kernel_launch(void* const* d_in, const int* in_sizes, int n_in,
                              void* d_out, int out_size) {
    const float* x = (const float*)d_in[0];
    const int* ei  = (const int*)d_in[1];
    const int* row = ei;
    const int* col = ei + EE;
    const float* W[8];
    const float* b[8];
    for (int i = 0; i < 8; i++) {
        W[i] = (const float*)d_in[2 + 2 * i];
        b[i] = (const float*)d_in[3 + 2 * i];
    }
    float *bufA, *bufB, *dis, *enrm;
    __half *AhA, *AhB, *Wh;
    uint8_t *A8hA, *A8lA, *A8hB, *A8lB, *W8h, *W8l;
    int *cnt, *cur, *off, *bsum, *src;
    cudaGetSymbolAddress((void**)&bufA, g_bufA);
    cudaGetSymbolAddress((void**)&bufB, g_bufB);
    cudaGetSymbolAddress((void**)&AhA,  g_AhA);
    cudaGetSymbolAddress((void**)&AhB,  g_AhB);
    cudaGetSymbolAddress((void**)&A8hA, g_A8hA);
    cudaGetSymbolAddress((void**)&A8lA, g_A8lA);
    cudaGetSymbolAddress((void**)&A8hB, g_A8hB);
    cudaGetSymbolAddress((void**)&A8lB, g_A8lB);
    cudaGetSymbolAddress((void**)&Wh,   g_Wh);
    cudaGetSymbolAddress((void**)&W8h,  g_W8h);
    cudaGetSymbolAddress((void**)&W8l,  g_W8l);
    cudaGetSymbolAddress((void**)&cnt,  g_cnt);
    cudaGetSymbolAddress((void**)&cur,  g_cur);
    cudaGetSymbolAddress((void**)&off,  g_off);
    cudaGetSymbolAddress((void**)&bsum, g_bsum);
    cudaGetSymbolAddress((void**)&dis,  g_dis);
    cudaGetSymbolAddress((void**)&src,  g_src);
    cudaGetSymbolAddress((void**)&enrm, g_enrm);
    float* out = (float*)d_out;

    cudaFuncSetAttribute(k_mma_gemm<true, true>,
                         cudaFuncAttributeMaxDynamicSharedMemorySize, MG_SMEM);
    cudaFuncSetAttribute(k_mma_gemm<false, false>,
                         cudaFuncAttributeMaxDynamicSharedMemorySize, MG_SMEM);

    // ---- CSR build ----
    k_zero2<<<(NN + 255) / 256, 256>>>(cnt, cur);
    k_cnt<<<(EE + 255) / 256, 256>>>(col, cnt);
    k_scan1<<<SCAN_NB, SCAN_BS>>>(cnt, off, bsum);
    k_scan2<<<1, 128>>>(bsum);
    k_scan3<<<(NN + 255) / 256, 256>>>(off, bsum);
    k_disk<<<(NN + 255) / 256, 256>>>(cnt, dis);
    k_fill<<<(EE + 255) / 256, 256>>>(row, col, dis, off, cur, src, enrm);

    // ---- L0: 3 -> 64 ----
    k_gather1<3, false><<<(NN * 3 + 255) / 256, 256>>>(x, off, src, enrm, dis, nullptr, bufA);
    k_l0_gemm<<<(NN * 64 + 255) / 256, 256>>>(bufA, W[0], b[0], bufB);

    // ---- L1-L3 (SIMT fp32) ----
    k_gather4<64, false, false, false><<<(NN * 16 + 255) / 256, 256>>>(
        (const float4*)bufB, off, src, enrm, dis, nullptr, (float4*)bufA, nullptr, nullptr, nullptr);
    k_gemm<true, true><<<dim3(1, (NN + 127) / 128), 256>>>(bufA, W[1], b[1], bufB, NN, 64, 64);

    k_gather4<64, false, false, false><<<(NN * 16 + 255) / 256, 256>>>(
        (const float4*)bufB, off, src, enrm, dis, nullptr, (float4*)bufA, nullptr, nullptr, nullptr);
    k_gemm<true, true><<<dim3(1, (NN + 127) / 128), 256>>>(bufA, W[2], b[2], bufB, NN, 64, 64);

    k_gather4<64, false, false, false><<<(NN * 16 + 255) / 256, 256>>>(
        (const float4*)bufB, off, src, enrm, dis, nullptr, (float4*)bufA, nullptr, nullptr, nullptr);
    k_gemm<true, true><<<dim3(2, (NN + 127) / 128), 256>>>(bufA, W[3], b[3], bufB, NN, 128, 64);

    // ---- L4: 128 -> 1024 (gather->split trio, mma with bias+relu, split-trio output) ----
    k_gather4<128, false, false, true><<<(NN * 32 + 255) / 256, 256>>>(
        (const float4*)bufB, off, src, enrm, dis, nullptr, nullptr,
        (__half2*)AhA, (uint32_t*)A8hA, (uint32_t*)A8lA);
    k_wsplit<<<(1024 * 128 + 255) / 256, 256>>>(W[4], Wh, W8h, W8l, 128, 1024);
    k_mma_gemm<true, true><<<dim3(4, (NN + 127) / 128), 256, MG_SMEM>>>(
        AhA, A8hA, A8lA, Wh, W8h, W8l, b[4], nullptr,
        (__half2*)AhB, (uint16_t*)A8hB, (uint16_t*)A8lB, NN, 1024, 128);

    // ---- L5: 1024 -> 512 (mma fp32 out; gather fuses bias+relu+split) ----
    k_wsplit<<<(512 * 1024 + 255) / 256, 256>>>(W[5], Wh, W8h, W8l, 1024, 512);
    k_mma_gemm<false, false><<<dim3(2, (NN + 127) / 128), 256, MG_SMEM>>>(
        AhB, A8hB, A8lB, Wh, W8h, W8l, nullptr, bufA, nullptr, nullptr, nullptr, NN, 512, 1024);
    k_gather4<512, true, true, true><<<(NN * 128 + 255) / 256, 256>>>(
        (const float4*)bufA, off, src, enrm, dis, b[5], nullptr,
        (__half2*)AhA, (uint32_t*)A8hA, (uint32_t*)A8lA);

    // ---- L6: 512 -> 256 (mma fp32 out; gather fuses bias; relu in L7 load) ----
    k_wsplit<<<(256 * 512 + 255) / 256, 256>>>(W[6], Wh, W8h, W8l, 512, 256);
    k_mma_gemm<false, false><<<dim3(1, (NN + 127) / 128), 256, MG_SMEM>>>(
        AhA, A8hA, A8lA, Wh, W8h, W8l, nullptr, bufB, nullptr, nullptr, nullptr, NN, 256, 512);
    k_gather4<256, true, false, false><<<(NN * 64 + 255) / 256, 256>>>(
        (const float4*)bufB, off, src, enrm, dis, b[6], (float4*)bufA, nullptr, nullptr, nullptr);

    // ---- L7: 256 -> 2 (relu fused into gemm load; gather fuses bias, writes d_out) ----
    k_l7_gemm<<<(NN * 32 + 255) / 256, 256>>>(bufA, W[7], bufB);
    k_gather1<2, true><<<(NN * 2 + 255) / 256, 256>>>(bufB, off, src, enrm, dis, b[7], out);
}

// round 12
// speedup vs baseline: 1.2526x; 1.2526x over previous
#include <cuda_runtime.h>
#include <cuda_fp16.h>
#include <cstdint>
#include <math.h>

#define NN 50000
#define EE 200000
#define SCAN_BS 512
#define SCAN_NB 98          // ceil(NN/512)

// ---------------- scratch (static device globals; allocation-free) ----------------
__device__ float g_bufA[(size_t)NN * 1024];
__device__ float g_bufB[(size_t)NN * 1024];
__device__ __half g_Ahi[(size_t)NN * 1024];
__device__ __half g_Alo[(size_t)NN * 1024];
__device__ __half g_Bhi[(size_t)NN * 1024];
__device__ __half g_Blo[(size_t)NN * 1024];
__device__ __half g_Wh[1024 * 1024];
__device__ __half g_Wl[1024 * 1024];
__device__ int   g_cnt[NN];
__device__ int   g_cur[NN];
__device__ int   g_off[NN + 1];
__device__ int   g_bsum[SCAN_NB];
__device__ float g_dis[NN];
__device__ int   g_src[EE];
__device__ float g_enrm[EE];

// ================= PTX helpers (arch-generic: sm_80+) =================
__device__ __forceinline__ uint32_t smem_to_u32(const void* p) {
    uint32_t a;
    asm("{ .reg .u64 t; cvta.to.shared.u64 t, %1; cvt.u32.u64 %0, t; }" : "=r"(a) : "l"(p));
    return a;
}
#define CP_ASYNC16(dst, src) \
    asm volatile("cp.async.cg.shared.global [%0], [%1], 16;" :: "r"(dst), "l"(src))
#define CP_COMMIT() asm volatile("cp.async.commit_group;" ::: "memory")
#define CP_WAIT(n)  asm volatile("cp.async.wait_group %0;" :: "n"(n) : "memory")
#define LDSM_X4(r0, r1, r2, r3, addr) \
    asm volatile("ldmatrix.sync.aligned.m8n8.x4.shared.b16 {%0,%1,%2,%3}, [%4];" \
        : "=r"(r0), "=r"(r1), "=r"(r2), "=r"(r3) : "r"(addr))
#define MMA_16816(c, a, b) \
    asm volatile("mma.sync.aligned.m16n8k16.row.col.f32.f16.f16.f32 " \
        "{%0,%1,%2,%3}, {%4,%5,%6,%7}, {%8,%9}, {%0,%1,%2,%3};" \
        : "+f"((c)[0]), "+f"((c)[1]), "+f"((c)[2]), "+f"((c)[3]) \
        : "r"((a)[0]), "r"((a)[1]), "r"((a)[2]), "r"((a)[3]), "r"((b)[0]), "r"((b)[1]))

// ================= CSR build =================
__global__ void k_zero2(int* __restrict__ a, int* __restrict__ b) {
    int i = blockIdx.x * blockDim.x + threadIdx.x;
    if (i < NN) { a[i] = 0; b[i] = 0; }
}
__global__ void k_cnt(const int* __restrict__ col, int* __restrict__ cnt) {
    int e = blockIdx.x * blockDim.x + threadIdx.x;
    if (e < EE) atomicAdd(&cnt[col[e]], 1);
}
__global__ void k_scan1(const int* __restrict__ cnt, int* __restrict__ off,
                        int* __restrict__ bsum) {
    __shared__ int sh[SCAN_BS];
    int tid = threadIdx.x;
    int i = blockIdx.x * SCAN_BS + tid;
    int v = (i < NN) ? cnt[i] : 0;
    sh[tid] = v;
    __syncthreads();
    #pragma unroll
    for (int d = 1; d < SCAN_BS; d <<= 1) {
        int t = (tid >= d) ? sh[tid - d] : 0;
        __syncthreads();
        sh[tid] += t;
        __syncthreads();
    }
    if (i < NN) off[i] = sh[tid] - v;          // exclusive
    if (tid == SCAN_BS - 1) bsum[blockIdx.x] = sh[tid];
}
__global__ void k_scan2(int* __restrict__ bsum) {
    __shared__ int sh[128];
    int tid = threadIdx.x;
    int v = (tid < SCAN_NB) ? bsum[tid] : 0;
    sh[tid] = v;
    __syncthreads();
    #pragma unroll
    for (int d = 1; d < 128; d <<= 1) {
        int t = (tid >= d) ? sh[tid - d] : 0;
        __syncthreads();
        sh[tid] += t;
        __syncthreads();
    }
    if (tid < SCAN_NB) bsum[tid] = sh[tid] - v;  // exclusive
}
// also computes dis = rsqrt(deg) (folded k_disk)
__global__ void k_scan3(int* __restrict__ off, const int* __restrict__ bsum,
                        const int* __restrict__ cnt, float* __restrict__ dis) {
    int i = blockIdx.x * blockDim.x + threadIdx.x;
    if (i < NN) {
        off[i] += bsum[i / SCAN_BS];
        dis[i] = rsqrtf((float)(cnt[i] + 1));
    }
    if (i == 0) off[NN] = EE;
}
__global__ void k_fill(const int* __restrict__ row, const int* __restrict__ col,
                       const float* __restrict__ dis, const int* __restrict__ off,
                       int* __restrict__ cur, int* __restrict__ src,
                       float* __restrict__ enrm) {
    int e = blockIdx.x * blockDim.x + threadIdx.x;
    if (e >= EE) return;
    int r = row[e], c = col[e];
    int pos = off[c] + atomicAdd(&cur[c], 1);
    src[pos] = r;
    enrm[pos] = dis[r] * dis[c];
}

// ================= fused CSR gather aggregation =================
template <int F, bool BIAS, bool RELU, bool SPLIT>
__global__ void __launch_bounds__(256) k_gather4(
    const float4* __restrict__ h, const int* __restrict__ off,
    const int* __restrict__ src, const float* __restrict__ enrm,
    const float* __restrict__ dis, const float* __restrict__ bias,
    float4* __restrict__ outf, __half2* __restrict__ ohi, __half2* __restrict__ olo) {
    constexpr int FV = F / 4;
    int idx = blockIdx.x * blockDim.x + threadIdx.x;
    if (idx >= NN * FV) return;
    int i = idx / FV;
    int f4 = idx - i * FV;
    float d = dis[i];
    float s = d * d;
    float4 v = h[(size_t)i * FV + f4];
    float4 acc;
    acc.x = s * v.x; acc.y = s * v.y; acc.z = s * v.z; acc.w = s * v.w;
    int p0 = off[i], p1 = off[i + 1];
    for (int p = p0; p < p1; p++) {
        int sn = src[p];
        float w = enrm[p];
        float4 u = h[(size_t)sn * FV + f4];
        acc.x += w * u.x; acc.y += w * u.y; acc.z += w * u.z; acc.w += w * u.w;
    }
    if (BIAS) {
        const float4 bv = *(const float4*)(bias + f4 * 4);
        acc.x += bv.x; acc.y += bv.y; acc.z += bv.z; acc.w += bv.w;
    }
    if (RELU) {
        acc.x = fmaxf(acc.x, 0.f); acc.y = fmaxf(acc.y, 0.f);
        acc.z = fmaxf(acc.z, 0.f); acc.w = fmaxf(acc.w, 0.f);
    }
    if (SPLIT) {
        __half hx = __float2half(acc.x), hy = __float2half(acc.y);
        __half hz = __float2half(acc.z), hw = __float2half(acc.w);
        __half lx = __float2half(acc.x - __half2float(hx));
        __half ly = __float2half(acc.y - __half2float(hy));
        __half lz = __float2half(acc.z - __half2float(hz));
        __half lw = __float2half(acc.w - __half2float(hw));
        ohi[(size_t)idx * 2 + 0] = __halves2half2(hx, hy);
        ohi[(size_t)idx * 2 + 1] = __halves2half2(hz, hw);
        olo[(size_t)idx * 2 + 0] = __halves2half2(lx, ly);
        olo[(size_t)idx * 2 + 1] = __halves2half2(lz, lw);
    } else {
        outf[idx] = acc;
    }
}

// scalar variant for F=3 and F=2
template <int F, bool BIAS>
__global__ void k_gather1(const float* __restrict__ h, const int* __restrict__ off,
                          const int* __restrict__ src, const float* __restrict__ enrm,
                          const float* __restrict__ dis, const float* __restrict__ bias,
                          float* __restrict__ outf) {
    int idx = blockIdx.x * blockDim.x + threadIdx.x;
    if (idx >= NN * F) return;
    int i = idx / F;
    int f = idx - i * F;
    float d = dis[i];
    float acc = d * d * h[(size_t)i * F + f];
    int p0 = off[i], p1 = off[i + 1];
    for (int p = p0; p < p1; p++)
        acc += enrm[p] * h[(size_t)src[p] * F + f];
    if (BIAS) acc += bias[f];
    outf[idx] = acc;
}

// ================= split-fp16 weight transpose =================
__global__ void k_wsplit(const float* __restrict__ W, __half* __restrict__ Wh,
                         __half* __restrict__ Wl, int K, int N) {
    int idx = blockIdx.x * blockDim.x + threadIdx.x;
    if (idx >= N * K) return;
    int n = idx / K;
    int k = idx - n * K;
    float v = W[(size_t)k * N + n];
    __half h = __float2half(v);
    Wh[idx] = h;
    Wl[idx] = __float2half(v - __half2float(h));
}

// ================= fused-product mma.sync split-fp16 GEMM =================
// C = AhWh + AlWh + AhWl (single K sweep).
// CTA tile 128x256, BK=32, 16 warps (2m x 8n), warp tile 64x32.
// 3-stage cp.async pipeline (prefetch depth 2) for DRAM latency hiding.
// Stage layout (61440 B): [Ah 10240][Al 10240][Bh 20480][Bl 20480]; 3 stages.
#define MG_RSTR  80
#define MG_AT    10240
#define MG_BT    20480
#define MG_ST4   61440
#define MG_SMEM  (3 * MG_ST4)

__device__ __forceinline__ void mg_load4(
    const __half* __restrict__ Ah_, const __half* __restrict__ Al_,
    const __half* __restrict__ Bh_, const __half* __restrict__ Bl_,
    int M, int K, int bm, int bn, int koff, uint32_t st, int tid) {
    // A hi / lo: 128 rows x 64B = 512 x 16B each; one CP per thread
    {
        int r = tid >> 2, ch = tid & 3;
        int gr = bm + r;
        if (gr >= M) gr = M - 1;
        CP_ASYNC16(st + r * MG_RSTR + ch * 16,
                   (const void*)(Ah_ + (size_t)gr * K + koff + ch * 8));
        CP_ASYNC16(st + MG_AT + r * MG_RSTR + ch * 16,
                   (const void*)(Al_ + (size_t)gr * K + koff + ch * 8));
    }
    // B hi / lo: 256 rows x 64B = 1024 x 16B each; two CPs per thread
    #pragma unroll
    for (int i = 0; i < 2; i++) {
        int idx = tid + i * 512;
        int r = idx >> 2, ch = idx & 3;
        CP_ASYNC16(st + 2 * MG_AT + r * MG_RSTR + ch * 16,
                   (const void*)(Bh_ + (size_t)(bn + r) * K + koff + ch * 8));
        CP_ASYNC16(st + 2 * MG_AT + MG_BT + r * MG_RSTR + ch * 16,
                   (const void*)(Bl_ + (size_t)(bn + r) * K + koff + ch * 8));
    }
    CP_COMMIT();
}

template <bool BIAS_RELU, bool SPLIT>
__global__ void __launch_bounds__(512, 1) k_mma_gemm(
    const __half* __restrict__ Ahi, const __half* __restrict__ Alo,
    const __half* __restrict__ Bhi, const __half* __restrict__ Blo,
    const float* __restrict__ bias, float* __restrict__ Cf,
    __half2* __restrict__ Chi, __half2* __restrict__ Clo,
    int M, int N, int K) {
    extern __shared__ __align__(16) char smx[];
    const uint32_t sbase = smem_to_u32(smx);
    const int tid = threadIdx.x;
    const int lane = tid & 31;
    const int wid = tid >> 5;            // 0..15
    const int wm = (wid & 1) * 64;       // 2 m-warps
    const int wn = (wid >> 1) * 32;      // 8 n-warps
    const int bm = blockIdx.y * 128;
    const int bn = blockIdx.x * 256;

    const int CK = K / 32;

    float acc[4][4][4];
    #pragma unroll
    for (int i = 0; i < 4; i++)
        #pragma unroll
        for (int j = 0; j < 4; j++)
            #pragma unroll
            for (int q = 0; q < 4; q++) acc[i][j][q] = 0.f;

    // prologue: prefetch stages 0 and 1
    mg_load4(Ahi, Alo, Bhi, Blo, M, K, bm, bn, 0, sbase, tid);
    if (CK > 1)
        mg_load4(Ahi, Alo, Bhi, Blo, M, K, bm, bn, 32, sbase + MG_ST4, tid);

    int sidx = 0;
    for (int c = 0; c < CK; c++) {
        if (c + 2 < CK) {
            int s2 = (sidx + 2) % 3;
            mg_load4(Ahi, Alo, Bhi, Blo, M, K, bm, bn, (c + 2) * 32,
                     sbase + s2 * MG_ST4, tid);
            CP_WAIT(2);
        } else if (c + 1 < CK) {
            CP_WAIT(1);
        } else {
            CP_WAIT(0);
        }
        __syncthreads();

        const uint32_t base = sbase + sidx * MG_ST4;
        #pragma unroll
        for (int kk = 0; kk < 32; kk += 16) {
            uint32_t ah[4][4], al[4][4];
            #pragma unroll
            for (int mi = 0; mi < 4; mi++) {
                int r = wm + mi * 16 + (lane & 15);
                int colb = (kk + ((lane >> 4) << 3)) * 2;
                LDSM_X4(ah[mi][0], ah[mi][1], ah[mi][2], ah[mi][3],
                        base + r * MG_RSTR + colb);
                LDSM_X4(al[mi][0], al[mi][1], al[mi][2], al[mi][3],
                        base + MG_AT + r * MG_RSTR + colb);
            }
            uint32_t bh[4][2], bl[4][2];
            #pragma unroll
            for (int nb = 0; nb < 2; nb++) {
                int n = wn + nb * 16 + (lane & 7) + ((lane >> 4) << 3);
                int colb = (kk + (((lane >> 3) & 1) << 3)) * 2;
                LDSM_X4(bh[2 * nb][0], bh[2 * nb][1], bh[2 * nb + 1][0], bh[2 * nb + 1][1],
                        base + 2 * MG_AT + n * MG_RSTR + colb);
                LDSM_X4(bl[2 * nb][0], bl[2 * nb][1], bl[2 * nb + 1][0], bl[2 * nb + 1][1],
                        base + 2 * MG_AT + MG_BT + n * MG_RSTR + colb);
            }
            #pragma unroll
            for (int mi = 0; mi < 4; mi++)
                #pragma unroll
                for (int nj = 0; nj < 4; nj++)
                    MMA_16816(acc[mi][nj], ah[mi], bh[nj]);
            #pragma unroll
            for (int mi = 0; mi < 4; mi++)
                #pragma unroll
                for (int nj = 0; nj < 4; nj++)
                    MMA_16816(acc[mi][nj], al[mi], bh[nj]);
            #pragma unroll
            for (int mi = 0; mi < 4; mi++)
                #pragma unroll
                for (int nj = 0; nj < 4; nj++)
                    MMA_16816(acc[mi][nj], ah[mi], bl[nj]);
        }
        __syncthreads();
        sidx = (sidx + 1) % 3;
    }

    // epilogue
    #pragma unroll
    for (int mi = 0; mi < 4; mi++) {
        int r0 = bm + wm + mi * 16 + (lane >> 2);
        #pragma unroll
        for (int nj = 0; nj < 4; nj++) {
            int cn = bn + wn + nj * 8 + (lane & 3) * 2;
            float2 v0, v1;
            v0.x = acc[mi][nj][0]; v0.y = acc[mi][nj][1];
            v1.x = acc[mi][nj][2]; v1.y = acc[mi][nj][3];
            if (BIAS_RELU) {
                float b0 = bias[cn], b1 = bias[cn + 1];
                v0.x = fmaxf(v0.x + b0, 0.f); v0.y = fmaxf(v0.y + b1, 0.f);
                v1.x = fmaxf(v1.x + b0, 0.f); v1.y = fmaxf(v1.y + b1, 0.f);
            }
            if (SPLIT) {
                #pragma unroll
                for (int rr = 0; rr < 2; rr++) {
                    int r = r0 + rr * 8;
                    if (r < M) {
                        float2 v = rr ? v1 : v0;
                        __half hx = __float2half(v.x), hy = __float2half(v.y);
                        __half lx = __float2half(v.x - __half2float(hx));
                        __half ly = __float2half(v.y - __half2float(hy));
                        size_t o = ((size_t)r * N + cn) >> 1;
                        Chi[o] = __halves2half2(hx, hy);
                        Clo[o] = __halves2half2(lx, ly);
                    }
                }
            } else {
                if (r0 < M)     *(float2*)(Cf + (size_t)r0 * N + cn) = v0;
                if (r0 + 8 < M) *(float2*)(Cf + (size_t)(r0 + 8) * N + cn) = v1;
            }
        }
    }
}

// ================= SIMT GEMM (small layers L1-L3) =================
template <bool RELU, bool BIAS>
__global__ void __launch_bounds__(256) k_gemm(
    const float* __restrict__ A, const float* __restrict__ B,
    const float* __restrict__ bias, float* __restrict__ C,
    int M, int N, int K) {
    constexpr int BMx = 128, BNx = 64, BK = 16, TM = 8, TN = 4;
    constexpr int AST = BMx + 4;
    __shared__ float As[BK * AST];
    __shared__ float Bs[BK * BNx];
    const int tid = threadIdx.x;
    const int bm = blockIdx.y * BMx;
    const int bn = blockIdx.x * BNx;
    const int tx = tid & 15;
    const int ty = tid >> 4;
    const int ar = tid >> 2;
    const int ac = (tid & 3) * 4;
    const int br = tid >> 4;
    const int bc = (tid & 15) * 4;
    float acc[TM][TN] = {};
    for (int kt = 0; kt < K; kt += BK) {
        #pragma unroll
        for (int i = 0; i < 2; i++) {
            int r = ar + i * 64;
            int gr = bm + r;
            float4 v = make_float4(0.f, 0.f, 0.f, 0.f);
            if (gr < M) v = *(const float4*)(A + (size_t)gr * K + kt + ac);
            As[(ac + 0) * AST + r] = v.x;
            As[(ac + 1) * AST + r] = v.y;
            As[(ac + 2) * AST + r] = v.z;
            As[(ac + 3) * AST + r] = v.w;
        }
        {
            float4 v = *(const float4*)(B + (size_t)(kt + br) * N + bn + bc);
            *(float4*)(Bs + br * BNx + bc) = v;
        }
        __syncthreads();
        #pragma unroll
        for (int k = 0; k < BK; k++) {
            float ra[TM], rb[TN];
            float4 a0 = *(const float4*)(As + k * AST + ty * TM);
            float4 a1 = *(const float4*)(As + k * AST + ty * TM + 4);
            ra[0] = a0.x; ra[1] = a0.y; ra[2] = a0.z; ra[3] = a0.w;
            ra[4] = a1.x; ra[5] = a1.y; ra[6] = a1.z; ra[7] = a1.w;
            float4 b0 = *(const float4*)(Bs + k * BNx + tx * TN);
            rb[0] = b0.x; rb[1] = b0.y; rb[2] = b0.z; rb[3] = b0.w;
            #pragma unroll
            for (int m = 0; m < TM; m++)
                #pragma unroll
                for (int n = 0; n < TN; n++)
                    acc[m][n] += ra[m] * rb[n];
        }
        __syncthreads();
    }
    float bv[TN] = {0.f, 0.f, 0.f, 0.f};
    if (BIAS) {
        float4 t = *(const float4*)(bias + bn + tx * TN);
        bv[0] = t.x; bv[1] = t.y; bv[2] = t.z; bv[3] = t.w;
    }
    #pragma unroll
    for (int m = 0; m < TM; m++) {
        int gr = bm + ty * TM + m;
        if (gr < M) {
            float4 o;
            o.x = acc[m][0] + bv[0];
            o.y = acc[m][1] + bv[1];
            o.z = acc[m][2] + bv[2];
            o.w = acc[m][3] + bv[3];
            if (RELU) {
                o.x = fmaxf(o.x, 0.f); o.y = fmaxf(o.y, 0.f);
                o.z = fmaxf(o.z, 0.f); o.w = fmaxf(o.w, 0.f);
            }
            *(float4*)(C + (size_t)gr * N + bn + tx * TN) = o;
        }
    }
}

// ---------------- layer-0 GEMM (K=3, Fout=64, bias+relu) ----------------
__global__ void k_l0_gemm(const float* __restrict__ t, const float* __restrict__ W,
                          const float* __restrict__ b, float* __restrict__ y) {
    int idx = blockIdx.x * blockDim.x + threadIdx.x;
    if (idx >= NN * 64) return;
    int i = idx >> 6;
    int j = idx & 63;
    float acc = b[j];
    acc += t[i * 3 + 0] * W[0 * 64 + j];
    acc += t[i * 3 + 1] * W[1 * 64 + j];
    acc += t[i * 3 + 2] * W[2 * 64 + j];
    y[idx] = fmaxf(acc, 0.f);
}

// ---------------- layer-7 GEMM (K=256, Fout=2) with fused input relu ----
__global__ void k_l7_gemm(const float* __restrict__ x, const float* __restrict__ W,
                          float* __restrict__ h) {
    int gwarp = (blockIdx.x * blockDim.x + threadIdx.x) >> 5;
    int lane = threadIdx.x & 31;
    if (gwarp >= NN) return;
    const float4* xr = (const float4*)(x + (size_t)gwarp * 256);
    float a0 = 0.f, a1 = 0.f;
    #pragma unroll
    for (int it = 0; it < 2; it++) {
        int c4 = lane + it * 32;
        float4 v = xr[c4];
        v.x = fmaxf(v.x, 0.f); v.y = fmaxf(v.y, 0.f);
        v.z = fmaxf(v.z, 0.f); v.w = fmaxf(v.w, 0.f);
        int k = c4 * 4;
        a0 += v.x * W[(k + 0) * 2 + 0] + v.y * W[(k + 1) * 2 + 0]
            + v.z * W[(k + 2) * 2 + 0] + v.w * W[(k + 3) * 2 + 0];
        a1 += v.x * W[(k + 0) * 2 + 1] + v.y * W[(k + 1) * 2 + 1]
            + v.z * W[(k + 2) * 2 + 1] + v.w * W[(k + 3) * 2 + 1];
    }
    #pragma unroll
    for (int off = 16; off > 0; off >>= 1) {
        a0 += __shfl_down_sync(0xFFFFFFFFu, a0, off);
        a1 += __shfl_down_sync(0xFFFFFFFFu, a1, off);
    }
    if (lane == 0) {
        h[gwarp * 2 + 0] = a0;
        h[gwarp * 2 + 1] = a1;
    }
}

// ================= host orchestration =================
extern "C" void kernel_launch(void* const* d_in, const int* in_sizes, int n_in,
                              void* d_out, int out_size) {
    const float* x = (const float*)d_in[0];
    const int* ei  = (const int*)d_in[1];
    const int* row = ei;
    const int* col = ei + EE;
    const float* W[8];
    const float* b[8];
    for (int i = 0; i < 8; i++) {
        W[i] = (const float*)d_in[2 + 2 * i];
        b[i] = (const float*)d_in[3 + 2 * i];
    }
    float *bufA, *bufB, *dis, *enrm;
    __half *Ahi, *Alo, *Bhi, *Blo, *Wh, *Wl;
    int *cnt, *cur, *off, *bsum, *src;
    cudaGetSymbolAddress((void**)&bufA, g_bufA);
    cudaGetSymbolAddress((void**)&bufB, g_bufB);
    cudaGetSymbolAddress((void**)&Ahi,  g_Ahi);
    cudaGetSymbolAddress((void**)&Alo,  g_Alo);
    cudaGetSymbolAddress((void**)&Bhi,  g_Bhi);
    cudaGetSymbolAddress((void**)&Blo,  g_Blo);
    cudaGetSymbolAddress((void**)&Wh,   g_Wh);
    cudaGetSymbolAddress((void**)&Wl,   g_Wl);
    cudaGetSymbolAddress((void**)&cnt,  g_cnt);
    cudaGetSymbolAddress((void**)&cur,  g_cur);
    cudaGetSymbolAddress((void**)&off,  g_off);
    cudaGetSymbolAddress((void**)&bsum, g_bsum);
    cudaGetSymbolAddress((void**)&dis,  g_dis);
    cudaGetSymbolAddress((void**)&src,  g_src);
    cudaGetSymbolAddress((void**)&enrm, g_enrm);
    float* out = (float*)d_out;

    cudaFuncSetAttribute(k_mma_gemm<true, true>,
                         cudaFuncAttributeMaxDynamicSharedMemorySize, MG_SMEM);
    cudaFuncSetAttribute(k_mma_gemm<false, false>,
                         cudaFuncAttributeMaxDynamicSharedMemorySize, MG_SMEM);

    // ---- CSR build ----
    k_zero2<<<(NN + 255) / 256, 256>>>(cnt, cur);
    k_cnt<<<(EE + 255) / 256, 256>>>(col, cnt);
    k_scan1<<<SCAN_NB, SCAN_BS>>>(cnt, off, bsum);
    k_scan2<<<1, 128>>>(bsum);
    k_scan3<<<(NN + 255) / 256, 256>>>(off, bsum, cnt, dis);
    k_fill<<<(EE + 255) / 256, 256>>>(row, col, dis, off, cur, src, enrm);

    // ---- L0: 3 -> 64 ----
    k_gather1<3, false><<<(NN * 3 + 255) / 256, 256>>>(x, off, src, enrm, dis, nullptr, bufA);
    k_l0_gemm<<<(NN * 64 + 255) / 256, 256>>>(bufA, W[0], b[0], bufB);

    // ---- L1-L3 (SIMT fp32) ----
    k_gather4<64, false, false, false><<<(NN * 16 + 255) / 256, 256>>>(
        (const float4*)bufB, off, src, enrm, dis, nullptr, (float4*)bufA, nullptr, nullptr);
    k_gemm<true, true><<<dim3(1, (NN + 127) / 128), 256>>>(bufA, W[1], b[1], bufB, NN, 64, 64);

    k_gather4<64, false, false, false><<<(NN * 16 + 255) / 256, 256>>>(
        (const float4*)bufB, off, src, enrm, dis, nullptr, (float4*)bufA, nullptr, nullptr);
    k_gemm<true, true><<<dim3(1, (NN + 127) / 128), 256>>>(bufA, W[2], b[2], bufB, NN, 64, 64);

    k_gather4<64, false, false, false><<<(NN * 16 + 255) / 256, 256>>>(
        (const float4*)bufB, off, src, enrm, dis, nullptr, (float4*)bufA, nullptr, nullptr);
    k_gemm<true, true><<<dim3(2, (NN + 127) / 128), 256>>>(bufA, W[3], b[3], bufB, NN, 128, 64);

    // ---- L4: 128 -> 1024 (gather->split, mma with bias+relu, split output) ----
    k_gather4<128, false, false, true><<<(NN * 32 + 255) / 256, 256>>>(
        (const float4*)bufB, off, src, enrm, dis, nullptr, nullptr, (__half2*)Ahi, (__half2*)Alo);
    k_wsplit<<<(1024 * 128 + 255) / 256, 256>>>(W[4], Wh, Wl, 128, 1024);
    k_mma_gemm<true, true><<<dim3(4, (NN + 127) / 128), 512, MG_SMEM>>>(
        Ahi, Alo, Wh, Wl, b[4], nullptr, (__half2*)Bhi, (__half2*)Blo, NN, 1024, 128);

    // ---- L5: 1024 -> 512 (mma fp32 out; gather fuses bias+relu+split) ----
    k_wsplit<<<(512 * 1024 + 255) / 256, 256>>>(W[5], Wh, Wl, 1024, 512);
    k_mma_gemm<false, false><<<dim3(2, (NN + 127) / 128), 512, MG_SMEM>>>(
        Bhi, Blo, Wh, Wl, nullptr, bufA, nullptr, nullptr, NN, 512, 1024);
    k_gather4<512, true, true, true><<<(NN * 128 + 255) / 256, 256>>>(
        (const float4*)bufA, off, src, enrm, dis, b[5], nullptr, (__half2*)Ahi, (__half2*)Alo);

    // ---- L6: 512 -> 256 (mma fp32 out; gather fuses bias; relu in L7 load) ----
    k_wsplit<<<(256 * 512 + 255) / 256, 256>>>(W[6], Wh, Wl, 512, 256);
    k_mma_gemm<false, false><<<dim3(1, (NN + 127) / 128), 512, MG_SMEM>>>(
        Ahi, Alo, Wh, Wl, nullptr, bufB, nullptr, nullptr, NN, 256, 512);
    k_gather4<256, true, false, false><<<(NN * 64 + 255) / 256, 256>>>(
        (const float4*)bufB, off, src, enrm, dis, b[6], (float4*)bufA, nullptr, nullptr);

    // ---- L7: 256 -> 2 (relu fused into gemm load; gather fuses bias, writes d_out) ----
    k_l7_gemm<<<(NN * 32 + 255) / 256, 256>>>(bufA, W[7], bufB);
    k_gather1<2, true><<<(NN * 2 + 255) / 256, 256>>>(bufB, off, src, enrm, dis, b[7], out);
}